// round 1
// baseline (speedup 1.0000x reference)
#include <cuda_runtime.h>
#include <math.h>

#define TT 4096      // SEQ_LEN
#define HH 2048      // D_HIDDEN
#define DM 4096      // D_MODEL
#define NCHUNK 64
#define CLEN (TT / NCHUNK)

// Scratch (static device arrays — no allocations allowed)
__device__ float g_bu_re[(size_t)TT * HH];
__device__ float g_bu_im[(size_t)TT * HH];
__device__ float g_hid_re[(size_t)TT * HH];
__device__ float g_hid_im[(size_t)TT * HH];
__device__ float g_lam_re[HH], g_lam_im[HH];
__device__ float g_lamL_re[HH], g_lamL_im[HH];
__device__ float g_gam[HH];
__device__ float g_chunk_re[NCHUNK * HH], g_chunk_im[NCHUNK * HH];
__device__ float g_carry_re[NCHUNK * HH], g_carry_im[NCHUNK * HH];

// ---------------------------------------------------------------------------
// Parameter precompute: lambda = exp(-exp(nu) + i*exp(theta)), gamma = exp(gl),
// lambda^CLEN for the chunk-carry scan.
// ---------------------------------------------------------------------------
__global__ void init_params(const float* __restrict__ nu_log,
                            const float* __restrict__ theta_log,
                            const float* __restrict__ gamma_log) {
    int h = blockIdx.x * blockDim.x + threadIdx.x;
    if (h >= HH) return;
    float nu  = expf(nu_log[h]);
    float th  = expf(theta_log[h]);
    float mag = expf(-nu);
    float lr  = mag * cosf(th);
    float li  = mag * sinf(th);
    g_lam_re[h] = lr;
    g_lam_im[h] = li;
    g_gam[h]    = expf(gamma_log[h]);
    float ar = 1.f, ai = 0.f;
    for (int i = 0; i < CLEN; i++) {
        float nr = ar * lr - ai * li;
        ai = ar * li + ai * lr;
        ar = nr;
    }
    g_lamL_re[h] = ar;
    g_lamL_im[h] = ai;
}

// ---------------------------------------------------------------------------
// GEMM1: Bu[t,h] = gamma[h] * sum_d x[t,d] * B[h,d]
// A: [TT, DM] row-major, B: [HH, DM] row-major, C: [TT, HH] row-major.
// 128x128 block tile, BK=16, 8x8 per-thread, 256 threads.
// which = 0 -> g_bu_re, which = 1 -> g_bu_im.
// ---------------------------------------------------------------------------
__global__ __launch_bounds__(256) void gemm_bu(
    const float* __restrict__ A,
    const float* __restrict__ B,
    int which)
{
    const int M = TT, N = HH, K = DM;
    (void)M;
    float* __restrict__ C = which ? g_bu_im : g_bu_re;

    __shared__ float As[16][128];
    __shared__ float Bs[16][128];

    const int bm  = blockIdx.y * 128;
    const int bn  = blockIdx.x * 128;
    const int tid = threadIdx.x;
    const int ty  = tid >> 4;   // 0..15
    const int tx  = tid & 15;   // 0..15

    float acc[8][8];
    #pragma unroll
    for (int i = 0; i < 8; i++)
        #pragma unroll
        for (int j = 0; j < 8; j++) acc[i][j] = 0.f;

    for (int kt = 0; kt < K; kt += 16) {
        #pragma unroll
        for (int i = 0; i < 2; i++) {
            int s   = tid + i * 256;     // 0..511
            int row = s >> 2;            // 0..127
            int c4  = s & 3;             // 0..3
            float4 va = *(const float4*)&A[(size_t)(bm + row) * K + kt + c4 * 4];
            As[c4 * 4 + 0][row] = va.x;
            As[c4 * 4 + 1][row] = va.y;
            As[c4 * 4 + 2][row] = va.z;
            As[c4 * 4 + 3][row] = va.w;
            float4 vb = *(const float4*)&B[(size_t)(bn + row) * K + kt + c4 * 4];
            Bs[c4 * 4 + 0][row] = vb.x;
            Bs[c4 * 4 + 1][row] = vb.y;
            Bs[c4 * 4 + 2][row] = vb.z;
            Bs[c4 * 4 + 3][row] = vb.w;
        }
        __syncthreads();
        #pragma unroll
        for (int k = 0; k < 16; k++) {
            float4 a0 = *(const float4*)&As[k][ty * 8];
            float4 a1 = *(const float4*)&As[k][ty * 8 + 4];
            float4 b0 = *(const float4*)&Bs[k][tx * 8];
            float4 b1 = *(const float4*)&Bs[k][tx * 8 + 4];
            float a[8] = {a0.x, a0.y, a0.z, a0.w, a1.x, a1.y, a1.z, a1.w};
            float b[8] = {b0.x, b0.y, b0.z, b0.w, b1.x, b1.y, b1.z, b1.w};
            #pragma unroll
            for (int i = 0; i < 8; i++)
                #pragma unroll
                for (int j = 0; j < 8; j++)
                    acc[i][j] = fmaf(a[i], b[j], acc[i][j]);
        }
        __syncthreads();
    }

    float gsc[8];
    #pragma unroll
    for (int j = 0; j < 8; j++) gsc[j] = g_gam[bn + tx * 8 + j];

    #pragma unroll
    for (int i = 0; i < 8; i++) {
        int row = bm + ty * 8 + i;
        float4 v0, v1;
        v0.x = acc[i][0] * gsc[0]; v0.y = acc[i][1] * gsc[1];
        v0.z = acc[i][2] * gsc[2]; v0.w = acc[i][3] * gsc[3];
        v1.x = acc[i][4] * gsc[4]; v1.y = acc[i][5] * gsc[5];
        v1.z = acc[i][6] * gsc[6]; v1.w = acc[i][7] * gsc[7];
        *(float4*)&C[(size_t)row * N + bn + tx * 8]     = v0;
        *(float4*)&C[(size_t)row * N + bn + tx * 8 + 4] = v1;
    }
}

// ---------------------------------------------------------------------------
// Scan pass 1: per-chunk local scan with zero init; record chunk-final state.
// ---------------------------------------------------------------------------
__global__ void scan_chunks() {
    int h = blockIdx.x * blockDim.x + threadIdx.x;   // 0..HH-1
    int c = blockIdx.y;                              // 0..NCHUNK-1
    float lr = g_lam_re[h], li = g_lam_im[h];
    float hr = 0.f, hi = 0.f;
    size_t base = (size_t)c * CLEN * HH + h;
    #pragma unroll 8
    for (int t = 0; t < CLEN; t++) {
        float br = g_bu_re[base + (size_t)t * HH];
        float bi = g_bu_im[base + (size_t)t * HH];
        float nr = fmaf(lr, hr, fmaf(-li, hi, br));
        float ni = fmaf(lr, hi, fmaf(li, hr, bi));
        hr = nr; hi = ni;
    }
    g_chunk_re[c * HH + h] = hr;
    g_chunk_im[c * HH + h] = hi;
}

// ---------------------------------------------------------------------------
// Scan pass 2: sequential scan over chunk-final states -> carry into each chunk.
// ---------------------------------------------------------------------------
__global__ void scan_carry() {
    int h = blockIdx.x * blockDim.x + threadIdx.x;
    float ar = g_lamL_re[h], ai = g_lamL_im[h];
    float cr = 0.f, ci = 0.f;
    for (int c = 0; c < NCHUNK; c++) {
        g_carry_re[c * HH + h] = cr;
        g_carry_im[c * HH + h] = ci;
        float pr = g_chunk_re[c * HH + h];
        float pi = g_chunk_im[c * HH + h];
        float nr = fmaf(ar, cr, fmaf(-ai, ci, pr));
        float ni = fmaf(ar, ci, fmaf(ai, cr, pi));
        cr = nr; ci = ni;
    }
}

// ---------------------------------------------------------------------------
// Scan pass 3: per-chunk final scan seeded with carry; write full hidden state.
// ---------------------------------------------------------------------------
__global__ void scan_final() {
    int h = blockIdx.x * blockDim.x + threadIdx.x;
    int c = blockIdx.y;
    float lr = g_lam_re[h], li = g_lam_im[h];
    float hr = g_carry_re[c * HH + h];
    float hi = g_carry_im[c * HH + h];
    size_t base = (size_t)c * CLEN * HH + h;
    #pragma unroll 8
    for (int t = 0; t < CLEN; t++) {
        float br = g_bu_re[base + (size_t)t * HH];
        float bi = g_bu_im[base + (size_t)t * HH];
        float nr = fmaf(lr, hr, fmaf(-li, hi, br));
        float ni = fmaf(lr, hi, fmaf(li, hr, bi));
        hr = nr; hi = ni;
        g_hid_re[base + (size_t)t * HH] = hr;
        g_hid_im[base + (size_t)t * HH] = hi;
    }
}

// ---------------------------------------------------------------------------
// GEMM2 (fused complex-real output):
// out[t,d] = sum_h hid_re[t,h]*Cre[d,h] - hid_im[t,h]*Cim[d,h] + x[t,d]*D[d]
// ---------------------------------------------------------------------------
__global__ __launch_bounds__(256) void gemm_out(
    const float* __restrict__ Cre,   // [DM, HH]
    const float* __restrict__ Cim,   // [DM, HH]
    const float* __restrict__ x,     // [TT, DM]
    const float* __restrict__ Dvec,  // [DM]
    float* __restrict__ out)         // [TT, DM]
{
    const int N = DM, K = HH;
    __shared__ float A1s[16][128];
    __shared__ float A2s[16][128];
    __shared__ float B1s[16][128];
    __shared__ float B2s[16][128];

    const int bm  = blockIdx.y * 128;
    const int bn  = blockIdx.x * 128;
    const int tid = threadIdx.x;
    const int ty  = tid >> 4;
    const int tx  = tid & 15;

    float acc[8][8];
    #pragma unroll
    for (int i = 0; i < 8; i++)
        #pragma unroll
        for (int j = 0; j < 8; j++) acc[i][j] = 0.f;

    for (int kt = 0; kt < K; kt += 16) {
        #pragma unroll
        for (int i = 0; i < 2; i++) {
            int s   = tid + i * 256;
            int row = s >> 2;
            int c4  = s & 3;
            float4 v;
            v = *(const float4*)&g_hid_re[(size_t)(bm + row) * K + kt + c4 * 4];
            A1s[c4 * 4 + 0][row] = v.x; A1s[c4 * 4 + 1][row] = v.y;
            A1s[c4 * 4 + 2][row] = v.z; A1s[c4 * 4 + 3][row] = v.w;
            v = *(const float4*)&g_hid_im[(size_t)(bm + row) * K + kt + c4 * 4];
            A2s[c4 * 4 + 0][row] = v.x; A2s[c4 * 4 + 1][row] = v.y;
            A2s[c4 * 4 + 2][row] = v.z; A2s[c4 * 4 + 3][row] = v.w;
            v = *(const float4*)&Cre[(size_t)(bn + row) * K + kt + c4 * 4];
            B1s[c4 * 4 + 0][row] = v.x; B1s[c4 * 4 + 1][row] = v.y;
            B1s[c4 * 4 + 2][row] = v.z; B1s[c4 * 4 + 3][row] = v.w;
            v = *(const float4*)&Cim[(size_t)(bn + row) * K + kt + c4 * 4];
            B2s[c4 * 4 + 0][row] = v.x; B2s[c4 * 4 + 1][row] = v.y;
            B2s[c4 * 4 + 2][row] = v.z; B2s[c4 * 4 + 3][row] = v.w;
        }
        __syncthreads();
        #pragma unroll
        for (int k = 0; k < 16; k++) {
            float4 p0 = *(const float4*)&A1s[k][ty * 8];
            float4 p1 = *(const float4*)&A1s[k][ty * 8 + 4];
            float4 q0 = *(const float4*)&A2s[k][ty * 8];
            float4 q1 = *(const float4*)&A2s[k][ty * 8 + 4];
            float4 r0 = *(const float4*)&B1s[k][tx * 8];
            float4 r1 = *(const float4*)&B1s[k][tx * 8 + 4];
            float4 s0 = *(const float4*)&B2s[k][tx * 8];
            float4 s1 = *(const float4*)&B2s[k][tx * 8 + 4];
            float a1[8] = {p0.x, p0.y, p0.z, p0.w, p1.x, p1.y, p1.z, p1.w};
            float a2[8] = {q0.x, q0.y, q0.z, q0.w, q1.x, q1.y, q1.z, q1.w};
            float b1[8] = {r0.x, r0.y, r0.z, r0.w, r1.x, r1.y, r1.z, r1.w};
            float b2[8] = {s0.x, s0.y, s0.z, s0.w, s1.x, s1.y, s1.z, s1.w};
            #pragma unroll
            for (int i = 0; i < 8; i++)
                #pragma unroll
                for (int j = 0; j < 8; j++) {
                    acc[i][j] = fmaf(a1[i], b1[j], acc[i][j]);
                    acc[i][j] = fmaf(-a2[i], b2[j], acc[i][j]);
                }
        }
        __syncthreads();
    }

    float dsc[8];
    #pragma unroll
    for (int j = 0; j < 8; j++) dsc[j] = Dvec[bn + tx * 8 + j];

    #pragma unroll
    for (int i = 0; i < 8; i++) {
        int row = bm + ty * 8 + i;
        size_t off = (size_t)row * N + bn + tx * 8;
        float4 x0 = *(const float4*)&x[off];
        float4 x1 = *(const float4*)&x[off + 4];
        float4 v0, v1;
        v0.x = fmaf(x0.x, dsc[0], acc[i][0]);
        v0.y = fmaf(x0.y, dsc[1], acc[i][1]);
        v0.z = fmaf(x0.z, dsc[2], acc[i][2]);
        v0.w = fmaf(x0.w, dsc[3], acc[i][3]);
        v1.x = fmaf(x1.x, dsc[4], acc[i][4]);
        v1.y = fmaf(x1.y, dsc[5], acc[i][5]);
        v1.z = fmaf(x1.z, dsc[6], acc[i][6]);
        v1.w = fmaf(x1.w, dsc[7], acc[i][7]);
        *(float4*)&out[off]     = v0;
        *(float4*)&out[off + 4] = v1;
    }
}

// ---------------------------------------------------------------------------
extern "C" void kernel_launch(void* const* d_in, const int* in_sizes, int n_in,
                              void* d_out, int out_size) {
    (void)in_sizes; (void)n_in; (void)out_size;
    const float* x         = (const float*)d_in[0];   // [TT, DM]
    const float* nu_log    = (const float*)d_in[1];   // [HH]
    const float* theta_log = (const float*)d_in[2];   // [HH]
    const float* gamma_log = (const float*)d_in[3];   // [HH]
    const float* B_re      = (const float*)d_in[4];   // [HH, DM]
    const float* B_im      = (const float*)d_in[5];   // [HH, DM]
    const float* C_re      = (const float*)d_in[6];   // [DM, HH]
    const float* C_im      = (const float*)d_in[7];   // [DM, HH]
    const float* Dvec      = (const float*)d_in[8];   // [DM]
    float* out = (float*)d_out;

    init_params<<<(HH + 255) / 256, 256>>>(nu_log, theta_log, gamma_log);

    dim3 g1(HH / 128, TT / 128);   // (16, 32)
    gemm_bu<<<g1, 256>>>(x, B_re, 0);
    gemm_bu<<<g1, 256>>>(x, B_im, 1);

    dim3 gs(HH / 256, NCHUNK);     // (8, 64)
    scan_chunks<<<gs, 256>>>();
    scan_carry<<<HH / 256, 256>>>();
    scan_final<<<gs, 256>>>();

    dim3 g2(DM / 128, TT / 128);   // (32, 32)
    gemm_out<<<g2, 256>>>(C_re, C_im, x, Dvec, out);
}

// round 3
// speedup vs baseline: 3.1786x; 3.1786x over previous
#include <cuda_runtime.h>
#include <cuda_bf16.h>
#include <cstdint>
#include <math.h>

#define TT 4096      // SEQ_LEN (M for both GEMMs)
#define HH 2048      // D_HIDDEN
#define DM 4096      // D_MODEL
#define KK 4096      // K for both GEMMs
#define NN 4096      // N for both GEMMs
#define NCHUNK 64
#define CLEN 64

#define BM 128
#define BN 256
#define BK 64
#define STG_B 0x18000        // 96KB per stage
#define SMEM_TOT (2 * STG_B) // 192KB

// ---------------- device scratch (no allocations allowed) ----------------
__device__ __nv_bfloat16 g_x_hi[(size_t)TT * DM], g_x_lo[(size_t)TT * DM];
__device__ __nv_bfloat16 g_b_hi[(size_t)NN * KK], g_b_lo[(size_t)NN * KK]; // [gB_re; gB_im] rows
__device__ __nv_bfloat16 g_c_hi[(size_t)NN * KK], g_c_lo[(size_t)NN * KK]; // [C_re | -C_im] cols
__device__ __nv_bfloat16 g_h_hi[(size_t)TT * KK], g_h_lo[(size_t)TT * KK]; // hidden (re|im)
__device__ float g_bu[(size_t)TT * NN];                                    // Bu (re|im)
__device__ float g_lam_re[HH], g_lam_im[HH];
__device__ float g_lamL_re[HH], g_lamL_im[HH];
__device__ float g_gam[HH];
__device__ float g_chunk_re[NCHUNK * HH], g_chunk_im[NCHUNK * HH];
__device__ float g_carry_re[NCHUNK * HH], g_carry_im[NCHUNK * HH];

// ---------------- helpers ----------------
__device__ __forceinline__ uint32_t smem_u32(const void* p) {
    uint32_t a;
    asm("{ .reg .u64 t; cvta.to.shared.u64 t, %1; cvt.u32.u64 %0, t; }" : "=r"(a) : "l"(p));
    return a;
}
#define SWZ(o) ((o) ^ (((o) >> 3) & 0x70))

__device__ __forceinline__ void cpasync16(uint32_t dst, const void* src) {
    asm volatile("cp.async.cg.shared.global [%0], [%1], 16;" :: "r"(dst), "l"(src));
}
__device__ __forceinline__ void ldsm4(uint32_t (&r)[4], uint32_t addr) {
    asm volatile("ldmatrix.sync.aligned.m8n8.x4.shared.b16 {%0,%1,%2,%3}, [%4];"
                 : "=r"(r[0]), "=r"(r[1]), "=r"(r[2]), "=r"(r[3]) : "r"(addr));
}
__device__ __forceinline__ void mma16816(float* c, const uint32_t (&a)[4],
                                         uint32_t b0, uint32_t b1) {
    asm volatile(
        "mma.sync.aligned.m16n8k16.row.col.f32.bf16.bf16.f32 "
        "{%0,%1,%2,%3}, {%4,%5,%6,%7}, {%8,%9}, {%0,%1,%2,%3};"
        : "+f"(c[0]), "+f"(c[1]), "+f"(c[2]), "+f"(c[3])
        : "r"(a[0]), "r"(a[1]), "r"(a[2]), "r"(a[3]), "r"(b0), "r"(b1));
}

// ---------------- param precompute / conversions ----------------
__global__ void init_params(const float* __restrict__ nu_log,
                            const float* __restrict__ theta_log,
                            const float* __restrict__ gamma_log) {
    int h = blockIdx.x * blockDim.x + threadIdx.x;
    if (h >= HH) return;
    float nu = expf(nu_log[h]);
    float th = expf(theta_log[h]);
    float mag = expf(-nu);
    float lr = mag * cosf(th), li = mag * sinf(th);
    g_lam_re[h] = lr; g_lam_im[h] = li;
    g_gam[h] = expf(gamma_log[h]);
    float ar = 1.f, ai = 0.f;
    for (int i = 0; i < CLEN; i++) {
        float nr = ar * lr - ai * li;
        ai = ar * li + ai * lr; ar = nr;
    }
    g_lamL_re[h] = ar; g_lamL_im[h] = ai;
}

__device__ __forceinline__ void split2(float v, __nv_bfloat16* hi, __nv_bfloat16* lo, size_t i) {
    __nv_bfloat16 h = __float2bfloat16(v);
    hi[i] = h;
    lo[i] = __float2bfloat16(v - __bfloat162float(h));
}

__global__ void conv_x_k(const float* __restrict__ x) {
    size_t i = (size_t)blockIdx.x * blockDim.x + threadIdx.x;
    split2(x[i], g_x_hi, g_x_lo, i);
}
// B' row r: r<HH -> gamma[r]*B_re[r,:], else gamma[r-HH]*B_im[r-HH,:]
__global__ void conv_b_k(const float* __restrict__ Bre, const float* __restrict__ Bim) {
    size_t i = (size_t)blockIdx.x * blockDim.x + threadIdx.x;
    unsigned row = (unsigned)(i >> 12);          // /DM
    unsigned col = (unsigned)(i & (DM - 1));
    float v;
    if (row < HH) v = Bre[(size_t)row * DM + col] * g_gam[row];
    else          v = Bim[(size_t)(row - HH) * DM + col] * g_gam[row - HH];
    split2(v, g_b_hi, g_b_lo, i);
}
// C' row d, col j: j<HH -> C_re[d,j], else -C_im[d,j-HH]
__global__ void conv_c_k(const float* __restrict__ Cre, const float* __restrict__ Cim) {
    size_t i = (size_t)blockIdx.x * blockDim.x + threadIdx.x;
    unsigned d = (unsigned)(i >> 12);            // /KK
    unsigned j = (unsigned)(i & (KK - 1));
    float v;
    if (j < HH) v = Cre[(size_t)d * HH + j];
    else        v = -Cim[(size_t)d * HH + (j - HH)];
    split2(v, g_c_hi, g_c_lo, i);
}

// ---------------- split-bf16 GEMM, M=N=K=4096, 128x256 CTA tile ----------------
// MODE 0: g_bu = x @ B'^T            (A = x split, B = g_b split)
// MODE 1: out  = h @ C'^T + x*D      (A = g_h split, B = g_c split)
template <int MODE>
__global__ __launch_bounds__(256, 1) void gemm_split(
    const float* __restrict__ x, const float* __restrict__ Dvec, float* __restrict__ out)
{
    extern __shared__ char smem[];
    const uint32_t sb = smem_u32(smem);
    const __nv_bfloat16 *Ah, *Al, *Bh, *Bl;
    if (MODE == 0) { Ah = g_x_hi; Al = g_x_lo; Bh = g_b_hi; Bl = g_b_lo; }
    else           { Ah = g_h_hi; Al = g_h_lo; Bh = g_c_hi; Bl = g_c_lo; }

    const int tid = threadIdx.x, lane = tid & 31, wid = tid >> 5;
    const int wm = wid & 1, wn = wid >> 1;           // 2 x 4 warp grid
    const int bm = blockIdx.y * BM, bn = blockIdx.x * BN;

    float acc[4][8][4];
    #pragma unroll
    for (int a = 0; a < 4; a++)
        #pragma unroll
        for (int b = 0; b < 8; b++)
            #pragma unroll
            for (int q = 0; q < 4; q++) acc[a][b][q] = 0.f;

    auto load_stage = [&](int s, int c) {
        uint32_t base = sb + s * STG_B;
        int ko = c * BK;
        #pragma unroll
        for (int i = 0; i < 4; i++) {                 // A: 128 rows
            int idx = tid + i * 256;
            int row = idx >> 3, c16 = idx & 7;
            uint32_t so = SWZ(row * 128 + c16 * 16);
            size_t g = (size_t)(bm + row) * KK + ko + c16 * 8;
            cpasync16(base + so, Ah + g);
            cpasync16(base + 0x4000 + so, Al + g);
        }
        #pragma unroll
        for (int i = 0; i < 8; i++) {                 // B: 256 rows
            int idx = tid + i * 256;
            int row = idx >> 3, c16 = idx & 7;
            uint32_t so = SWZ(row * 128 + c16 * 16);
            size_t g = (size_t)(bn + row) * KK + ko + c16 * 8;
            cpasync16(base + 0x8000 + so, Bh + g);
            cpasync16(base + 0x10000 + so, Bl + g);
        }
        asm volatile("cp.async.commit_group;" ::: "memory");
    };

    load_stage(0, 0);
    const int KC = KK / BK;  // 64

    const int ar_ = lane & 15, ah_ = lane >> 4;
    const int nr_ = ((lane >> 4) << 3) + (lane & 7), nh_ = (lane >> 3) & 1;

    for (int c = 0; c < KC; ++c) {
        asm volatile("cp.async.wait_group 0;" ::: "memory");
        __syncthreads();
        if (c + 1 < KC) load_stage((c + 1) & 1, c + 1);

        uint32_t st = sb + (c & 1) * STG_B;
        #pragma unroll
        for (int ks = 0; ks < 4; ks++) {
            uint32_t a_h[4][4], a_l[4][4];
            #pragma unroll
            for (int mt = 0; mt < 4; mt++) {
                int row = wm * 64 + mt * 16 + ar_;
                uint32_t ad = st + SWZ(row * 128 + ks * 32 + ah_ * 16);
                ldsm4(a_h[mt], ad);
                ldsm4(a_l[mt], ad + 0x4000);
            }
            uint32_t b[4][4];
            #pragma unroll
            for (int bt = 0; bt < 4; bt++) {
                int row = wn * 64 + bt * 16 + nr_;
                ldsm4(b[bt], st + 0x8000 + SWZ(row * 128 + ks * 32 + nh_ * 16));
            }
            // Ah*Bh + Al*Bh
            #pragma unroll
            for (int mt = 0; mt < 4; mt++)
                #pragma unroll
                for (int bt = 0; bt < 4; bt++) {
                    mma16816(acc[mt][2 * bt],     a_h[mt], b[bt][0], b[bt][1]);
                    mma16816(acc[mt][2 * bt + 1], a_h[mt], b[bt][2], b[bt][3]);
                    mma16816(acc[mt][2 * bt],     a_l[mt], b[bt][0], b[bt][1]);
                    mma16816(acc[mt][2 * bt + 1], a_l[mt], b[bt][2], b[bt][3]);
                }
            // Ah*Bl (reuse b regs)
            #pragma unroll
            for (int bt = 0; bt < 4; bt++) {
                int row = wn * 64 + bt * 16 + nr_;
                ldsm4(b[bt], st + 0x10000 + SWZ(row * 128 + ks * 32 + nh_ * 16));
            }
            #pragma unroll
            for (int mt = 0; mt < 4; mt++)
                #pragma unroll
                for (int bt = 0; bt < 4; bt++) {
                    mma16816(acc[mt][2 * bt],     a_h[mt], b[bt][0], b[bt][1]);
                    mma16816(acc[mt][2 * bt + 1], a_h[mt], b[bt][2], b[bt][3]);
                }
        }
    }

    // epilogue
    const int r0 = bm + wm * 64 + (lane >> 2);
    const int c0 = bn + wn * 64 + (lane & 3) * 2;
    #pragma unroll
    for (int mt = 0; mt < 4; mt++) {
        #pragma unroll
        for (int nt = 0; nt < 8; nt++) {
            int row = r0 + mt * 16;
            int col = c0 + nt * 8;
            if (MODE == 0) {
                float2 v0 = make_float2(acc[mt][nt][0], acc[mt][nt][1]);
                float2 v1 = make_float2(acc[mt][nt][2], acc[mt][nt][3]);
                *(float2*)&g_bu[(size_t)row * NN + col]       = v0;
                *(float2*)&g_bu[(size_t)(row + 8) * NN + col] = v1;
            } else {
                float2 dv = *(const float2*)&Dvec[col];
                float2 x0 = *(const float2*)&x[(size_t)row * NN + col];
                float2 x1 = *(const float2*)&x[(size_t)(row + 8) * NN + col];
                float2 v0, v1;
                v0.x = fmaf(x0.x, dv.x, acc[mt][nt][0]);
                v0.y = fmaf(x0.y, dv.y, acc[mt][nt][1]);
                v1.x = fmaf(x1.x, dv.x, acc[mt][nt][2]);
                v1.y = fmaf(x1.y, dv.y, acc[mt][nt][3]);
                *(float2*)&out[(size_t)row * NN + col]       = v0;
                *(float2*)&out[(size_t)(row + 8) * NN + col] = v1;
            }
        }
    }
}

// ---------------- scan (layout: [TT, 4096] = re|im) ----------------
__global__ void scan_chunks() {
    int h = blockIdx.x * blockDim.x + threadIdx.x;   // 0..HH-1
    int c = blockIdx.y;
    float lr = g_lam_re[h], li = g_lam_im[h];
    float hr = 0.f, hi = 0.f;
    size_t base = (size_t)c * CLEN * NN + h;
    #pragma unroll 8
    for (int t = 0; t < CLEN; t++) {
        float br = g_bu[base + (size_t)t * NN];
        float bi = g_bu[base + (size_t)t * NN + HH];
        float nr = fmaf(lr, hr, fmaf(-li, hi, br));
        float ni = fmaf(lr, hi, fmaf(li, hr, bi));
        hr = nr; hi = ni;
    }
    g_chunk_re[c * HH + h] = hr;
    g_chunk_im[c * HH + h] = hi;
}

__global__ void scan_carry() {
    int h = blockIdx.x * blockDim.x + threadIdx.x;
    float ar = g_lamL_re[h], ai = g_lamL_im[h];
    float cr = 0.f, ci = 0.f;
    for (int c = 0; c < NCHUNK; c++) {
        g_carry_re[c * HH + h] = cr;
        g_carry_im[c * HH + h] = ci;
        float pr = g_chunk_re[c * HH + h];
        float pi = g_chunk_im[c * HH + h];
        float nr = fmaf(ar, cr, fmaf(-ai, ci, pr));
        float ni = fmaf(ar, ci, fmaf(ai, cr, pi));
        cr = nr; ci = ni;
    }
}

__global__ void scan_final() {
    int h = blockIdx.x * blockDim.x + threadIdx.x;
    int c = blockIdx.y;
    float lr = g_lam_re[h], li = g_lam_im[h];
    float hr = g_carry_re[c * HH + h];
    float hi = g_carry_im[c * HH + h];
    size_t base = (size_t)c * CLEN * NN + h;
    #pragma unroll 4
    for (int t = 0; t < CLEN; t++) {
        size_t ir = base + (size_t)t * NN;
        float br = g_bu[ir];
        float bi = g_bu[ir + HH];
        float nr = fmaf(lr, hr, fmaf(-li, hi, br));
        float ni = fmaf(lr, hi, fmaf(li, hr, bi));
        hr = nr; hi = ni;
        __nv_bfloat16 a = __float2bfloat16(hr);
        g_h_hi[ir] = a;
        g_h_lo[ir] = __float2bfloat16(hr - __bfloat162float(a));
        __nv_bfloat16 b = __float2bfloat16(hi);
        g_h_hi[ir + HH] = b;
        g_h_lo[ir + HH] = __float2bfloat16(hi - __bfloat162float(b));
    }
}

// ---------------- launch ----------------
extern "C" void kernel_launch(void* const* d_in, const int* in_sizes, int n_in,
                              void* d_out, int out_size) {
    (void)in_sizes; (void)n_in; (void)out_size;
    const float* x         = (const float*)d_in[0];
    const float* nu_log    = (const float*)d_in[1];
    const float* theta_log = (const float*)d_in[2];
    const float* gamma_log = (const float*)d_in[3];
    const float* B_re      = (const float*)d_in[4];
    const float* B_im      = (const float*)d_in[5];
    const float* C_re      = (const float*)d_in[6];
    const float* C_im      = (const float*)d_in[7];
    const float* Dvec      = (const float*)d_in[8];
    float* out = (float*)d_out;

    cudaFuncSetAttribute(gemm_split<0>, cudaFuncAttributeMaxDynamicSharedMemorySize, SMEM_TOT);
    cudaFuncSetAttribute(gemm_split<1>, cudaFuncAttributeMaxDynamicSharedMemorySize, SMEM_TOT);

    init_params<<<(HH + 255) / 256, 256>>>(nu_log, theta_log, gamma_log);
    conv_x_k<<<((size_t)TT * DM) / 256, 256>>>(x);
    conv_b_k<<<((size_t)NN * KK) / 256, 256>>>(B_re, B_im);
    conv_c_k<<<((size_t)NN * KK) / 256, 256>>>(C_re, C_im);

    dim3 gg(NN / BN, TT / BM);   // (16, 32)
    gemm_split<0><<<gg, 256, SMEM_TOT>>>(x, Dvec, out);

    dim3 gs(HH / 256, NCHUNK);
    scan_chunks<<<gs, 256>>>();
    scan_carry<<<HH / 256, 256>>>();
    scan_final<<<gs, 256>>>();

    gemm_split<1><<<gg, 256, SMEM_TOT>>>(x, Dvec, out);
}

// round 4
// speedup vs baseline: 3.5535x; 1.1180x over previous
#include <cuda_runtime.h>
#include <cuda_bf16.h>
#include <cstdint>
#include <math.h>

#define TT 4096      // SEQ_LEN (M for both GEMMs)
#define HH 2048      // D_HIDDEN
#define DM 4096      // D_MODEL
#define KK 4096      // K for both GEMMs
#define NN 4096      // N for both GEMMs
#define NCHUNK 64
#define CLEN 64

#define BM 128
#define BN 128
#define BK 64
#define STG_B 0x10000        // 64KB per stage
#define SMEM_TOT (2 * STG_B) // 128KB

// ---------------- device scratch (no allocations allowed) ----------------
__device__ __nv_bfloat16 g_x_hi[(size_t)TT * DM], g_x_lo[(size_t)TT * DM];
__device__ __nv_bfloat16 g_b_hi[(size_t)NN * KK], g_b_lo[(size_t)NN * KK]; // [gB_re; gB_im] rows
__device__ __nv_bfloat16 g_c_hi[(size_t)NN * KK], g_c_lo[(size_t)NN * KK]; // [C_re | -C_im] cols
__device__ __nv_bfloat16 g_h_hi[(size_t)TT * KK], g_h_lo[(size_t)TT * KK]; // hidden (re|im)
__device__ float g_bu[(size_t)TT * NN];                                    // Bu (re|im)
__device__ float g_lam_re[HH], g_lam_im[HH];
__device__ float g_lamL_re[HH], g_lamL_im[HH];
__device__ float g_gam[HH];
__device__ float g_chunk_re[NCHUNK * HH], g_chunk_im[NCHUNK * HH];
__device__ float g_carry_re[NCHUNK * HH], g_carry_im[NCHUNK * HH];

// ---------------- helpers ----------------
__device__ __forceinline__ uint32_t smem_u32(const void* p) {
    uint32_t a;
    asm("{ .reg .u64 t; cvta.to.shared.u64 t, %1; cvt.u32.u64 %0, t; }" : "=r"(a) : "l"(p));
    return a;
}
#define SWZ(o) ((o) ^ (((o) >> 3) & 0x70))

__device__ __forceinline__ void cpasync16(uint32_t dst, const void* src) {
    asm volatile("cp.async.cg.shared.global [%0], [%1], 16;" :: "r"(dst), "l"(src));
}
__device__ __forceinline__ void ldsm4(uint32_t (&r)[4], uint32_t addr) {
    asm volatile("ldmatrix.sync.aligned.m8n8.x4.shared.b16 {%0,%1,%2,%3}, [%4];"
                 : "=r"(r[0]), "=r"(r[1]), "=r"(r[2]), "=r"(r[3]) : "r"(addr));
}
__device__ __forceinline__ void mma16816(float* c, const uint32_t (&a)[4],
                                         uint32_t b0, uint32_t b1) {
    asm volatile(
        "mma.sync.aligned.m16n8k16.row.col.f32.bf16.bf16.f32 "
        "{%0,%1,%2,%3}, {%4,%5,%6,%7}, {%8,%9}, {%0,%1,%2,%3};"
        : "+f"(c[0]), "+f"(c[1]), "+f"(c[2]), "+f"(c[3])
        : "r"(a[0]), "r"(a[1]), "r"(a[2]), "r"(a[3]), "r"(b0), "r"(b1));
}

// pack 4 floats -> hi/lo bf16 pairs as 2x uint2
__device__ __forceinline__ void pack4(const float4 v, uint2& hi, uint2& lo) {
    __nv_bfloat16 h0 = __float2bfloat16(v.x);
    __nv_bfloat16 h1 = __float2bfloat16(v.y);
    __nv_bfloat16 h2 = __float2bfloat16(v.z);
    __nv_bfloat16 h3 = __float2bfloat16(v.w);
    __nv_bfloat162 hp0(h0, h1), hp1(h2, h3);
    __nv_bfloat162 lp0(__float2bfloat16(v.x - __bfloat162float(h0)),
                       __float2bfloat16(v.y - __bfloat162float(h1)));
    __nv_bfloat162 lp1(__float2bfloat16(v.z - __bfloat162float(h2)),
                       __float2bfloat16(v.w - __bfloat162float(h3)));
    hi.x = *(uint32_t*)&hp0; hi.y = *(uint32_t*)&hp1;
    lo.x = *(uint32_t*)&lp0; lo.y = *(uint32_t*)&lp1;
}

// ---------------- param precompute / conversions ----------------
__global__ void init_params(const float* __restrict__ nu_log,
                            const float* __restrict__ theta_log,
                            const float* __restrict__ gamma_log) {
    int h = blockIdx.x * blockDim.x + threadIdx.x;
    if (h >= HH) return;
    float nu = expf(nu_log[h]);
    float th = expf(theta_log[h]);
    float mag = expf(-nu);
    float lr = mag * cosf(th), li = mag * sinf(th);
    g_lam_re[h] = lr; g_lam_im[h] = li;
    g_gam[h] = expf(gamma_log[h]);
    float ar = 1.f, ai = 0.f;
    for (int i = 0; i < CLEN; i++) {
        float nr = ar * lr - ai * li;
        ai = ar * li + ai * lr; ar = nr;
    }
    g_lamL_re[h] = ar; g_lamL_im[h] = ai;
}

__global__ void conv_x_k(const float* __restrict__ x) {
    size_t q = (size_t)blockIdx.x * blockDim.x + threadIdx.x;   // quad index
    size_t i = q * 4;
    float4 v = *(const float4*)(x + i);
    uint2 hi, lo;
    pack4(v, hi, lo);
    *(uint2*)(g_x_hi + i) = hi;
    *(uint2*)(g_x_lo + i) = lo;
}

// B' row r: r<HH -> gamma[r]*B_re[r,:], else gamma[r-HH]*B_im[r-HH,:]
__global__ void conv_b_k(const float* __restrict__ Bre, const float* __restrict__ Bim) {
    size_t q = (size_t)blockIdx.x * blockDim.x + threadIdx.x;
    size_t i = q * 4;
    unsigned row = (unsigned)(i >> 12);
    float4 v;
    float g;
    if (row < HH) { v = *(const float4*)(Bre + i); g = g_gam[row]; }
    else          { v = *(const float4*)(Bim + (i - (size_t)HH * DM)); g = g_gam[row - HH]; }
    v.x *= g; v.y *= g; v.z *= g; v.w *= g;
    uint2 hi, lo;
    pack4(v, hi, lo);
    *(uint2*)(g_b_hi + i) = hi;
    *(uint2*)(g_b_lo + i) = lo;
}

// C' row d, col j: j<HH -> C_re[d,j], else -C_im[d,j-HH]
__global__ void conv_c_k(const float* __restrict__ Cre, const float* __restrict__ Cim) {
    size_t q = (size_t)blockIdx.x * blockDim.x + threadIdx.x;
    size_t i = q * 4;
    unsigned d = (unsigned)(i >> 12);
    unsigned j = (unsigned)(i & (KK - 1));
    float4 v;
    if (j < HH) {
        v = *(const float4*)(Cre + (size_t)d * HH + j);
    } else {
        v = *(const float4*)(Cim + (size_t)d * HH + (j - HH));
        v.x = -v.x; v.y = -v.y; v.z = -v.z; v.w = -v.w;
    }
    uint2 hi, lo;
    pack4(v, hi, lo);
    *(uint2*)(g_c_hi + i) = hi;
    *(uint2*)(g_c_lo + i) = lo;
}

// ---------------- split-bf16 GEMM, M=N=K=4096, 128x128 CTA tile ----------------
// MODE 0: g_bu = x @ B'^T            (A = x split, B = g_b split)
// MODE 1: out  = h @ C'^T + x*D      (A = g_h split, B = g_c split)
template <int MODE>
__global__ __launch_bounds__(256, 1) void gemm_split(
    const float* __restrict__ x, const float* __restrict__ Dvec, float* __restrict__ out)
{
    extern __shared__ char smem[];
    const uint32_t sb = smem_u32(smem);
    const __nv_bfloat16 *Ah, *Al, *Bh, *Bl;
    if (MODE == 0) { Ah = g_x_hi; Al = g_x_lo; Bh = g_b_hi; Bl = g_b_lo; }
    else           { Ah = g_h_hi; Al = g_h_lo; Bh = g_c_hi; Bl = g_c_lo; }

    const int tid = threadIdx.x, lane = tid & 31, wid = tid >> 5;
    const int wm = wid & 1, wn = wid >> 1;           // 2 x 4 warp grid -> 64x32 warp tile
    const int bm = blockIdx.y * BM, bn = blockIdx.x * BN;

    float acc[4][4][4];
    #pragma unroll
    for (int a = 0; a < 4; a++)
        #pragma unroll
        for (int b = 0; b < 4; b++)
            #pragma unroll
            for (int q = 0; q < 4; q++) acc[a][b][q] = 0.f;

    // stage layout: Ah 0x0000, Al 0x4000, Bh 0x8000, Bl 0xC000
    auto load_stage = [&](int s, int c) {
        uint32_t base = sb + s * STG_B;
        int ko = c * BK;
        #pragma unroll
        for (int i = 0; i < 4; i++) {                 // A: 128 rows
            int idx = tid + i * 256;
            int row = idx >> 3, c16 = idx & 7;
            uint32_t so = SWZ(row * 128 + c16 * 16);
            size_t g = (size_t)(bm + row) * KK + ko + c16 * 8;
            cpasync16(base + so, Ah + g);
            cpasync16(base + 0x4000 + so, Al + g);
        }
        #pragma unroll
        for (int i = 0; i < 4; i++) {                 // B: 128 rows
            int idx = tid + i * 256;
            int row = idx >> 3, c16 = idx & 7;
            uint32_t so = SWZ(row * 128 + c16 * 16);
            size_t g = (size_t)(bn + row) * KK + ko + c16 * 8;
            cpasync16(base + 0x8000 + so, Bh + g);
            cpasync16(base + 0xC000 + so, Bl + g);
        }
        asm volatile("cp.async.commit_group;" ::: "memory");
    };

    load_stage(0, 0);
    const int KC = KK / BK;  // 64

    const int ar_ = lane & 15, ah_ = lane >> 4;
    const int nr_ = ((lane >> 4) << 3) + (lane & 7), nh_ = (lane >> 3) & 1;

    for (int c = 0; c < KC; ++c) {
        asm volatile("cp.async.wait_group 0;" ::: "memory");
        __syncthreads();
        if (c + 1 < KC) load_stage((c + 1) & 1, c + 1);

        uint32_t st = sb + (c & 1) * STG_B;
        #pragma unroll
        for (int ks = 0; ks < 4; ks++) {
            uint32_t a_h[4][4], a_l[4][4];
            #pragma unroll
            for (int mt = 0; mt < 4; mt++) {
                int row = wm * 64 + mt * 16 + ar_;
                uint32_t ad = st + SWZ(row * 128 + ks * 32 + ah_ * 16);
                ldsm4(a_h[mt], ad);
                ldsm4(a_l[mt], ad + 0x4000);
            }
            uint32_t b[2][4];
            #pragma unroll
            for (int bt = 0; bt < 2; bt++) {
                int row = wn * 32 + bt * 16 + nr_;
                ldsm4(b[bt], st + 0x8000 + SWZ(row * 128 + ks * 32 + nh_ * 16));
            }
            // Ah*Bh + Al*Bh
            #pragma unroll
            for (int mt = 0; mt < 4; mt++)
                #pragma unroll
                for (int bt = 0; bt < 2; bt++) {
                    mma16816(acc[mt][2 * bt],     a_h[mt], b[bt][0], b[bt][1]);
                    mma16816(acc[mt][2 * bt + 1], a_h[mt], b[bt][2], b[bt][3]);
                    mma16816(acc[mt][2 * bt],     a_l[mt], b[bt][0], b[bt][1]);
                    mma16816(acc[mt][2 * bt + 1], a_l[mt], b[bt][2], b[bt][3]);
                }
            // Ah*Bl (reuse b regs)
            #pragma unroll
            for (int bt = 0; bt < 2; bt++) {
                int row = wn * 32 + bt * 16 + nr_;
                ldsm4(b[bt], st + 0xC000 + SWZ(row * 128 + ks * 32 + nh_ * 16));
            }
            #pragma unroll
            for (int mt = 0; mt < 4; mt++)
                #pragma unroll
                for (int bt = 0; bt < 2; bt++) {
                    mma16816(acc[mt][2 * bt],     a_h[mt], b[bt][0], b[bt][1]);
                    mma16816(acc[mt][2 * bt + 1], a_h[mt], b[bt][2], b[bt][3]);
                }
        }
    }

    // epilogue
    const int r0 = bm + wm * 64 + (lane >> 2);
    const int c0 = bn + wn * 32 + (lane & 3) * 2;
    #pragma unroll
    for (int mt = 0; mt < 4; mt++) {
        #pragma unroll
        for (int nt = 0; nt < 4; nt++) {
            int row = r0 + mt * 16;
            int col = c0 + nt * 8;
            if (MODE == 0) {
                float2 v0 = make_float2(acc[mt][nt][0], acc[mt][nt][1]);
                float2 v1 = make_float2(acc[mt][nt][2], acc[mt][nt][3]);
                *(float2*)&g_bu[(size_t)row * NN + col]       = v0;
                *(float2*)&g_bu[(size_t)(row + 8) * NN + col] = v1;
            } else {
                float2 dv = *(const float2*)&Dvec[col];
                float2 x0 = *(const float2*)&x[(size_t)row * NN + col];
                float2 x1 = *(const float2*)&x[(size_t)(row + 8) * NN + col];
                float2 v0, v1;
                v0.x = fmaf(x0.x, dv.x, acc[mt][nt][0]);
                v0.y = fmaf(x0.y, dv.y, acc[mt][nt][1]);
                v1.x = fmaf(x1.x, dv.x, acc[mt][nt][2]);
                v1.y = fmaf(x1.y, dv.y, acc[mt][nt][3]);
                *(float2*)&out[(size_t)row * NN + col]       = v0;
                *(float2*)&out[(size_t)(row + 8) * NN + col] = v1;
            }
        }
    }
}

// ---------------- scan (layout: [TT, 4096] = re|im) ----------------
__global__ void scan_chunks() {
    int h = blockIdx.x * blockDim.x + threadIdx.x;   // 0..HH-1
    int c = blockIdx.y;
    float lr = g_lam_re[h], li = g_lam_im[h];
    float hr = 0.f, hi = 0.f;
    size_t base = (size_t)c * CLEN * NN + h;
    #pragma unroll 8
    for (int t = 0; t < CLEN; t++) {
        float br = g_bu[base + (size_t)t * NN];
        float bi = g_bu[base + (size_t)t * NN + HH];
        float nr = fmaf(lr, hr, fmaf(-li, hi, br));
        float ni = fmaf(lr, hi, fmaf(li, hr, bi));
        hr = nr; hi = ni;
    }
    g_chunk_re[c * HH + h] = hr;
    g_chunk_im[c * HH + h] = hi;
}

__global__ void scan_carry() {
    int h = blockIdx.x * blockDim.x + threadIdx.x;
    float ar = g_lamL_re[h], ai = g_lamL_im[h];
    float cr = 0.f, ci = 0.f;
    for (int c = 0; c < NCHUNK; c++) {
        g_carry_re[c * HH + h] = cr;
        g_carry_im[c * HH + h] = ci;
        float pr = g_chunk_re[c * HH + h];
        float pi = g_chunk_im[c * HH + h];
        float nr = fmaf(ar, cr, fmaf(-ai, ci, pr));
        float ni = fmaf(ar, ci, fmaf(ai, cr, pi));
        cr = nr; ci = ni;
    }
}

__global__ void scan_final() {
    int h = blockIdx.x * blockDim.x + threadIdx.x;
    int c = blockIdx.y;
    float lr = g_lam_re[h], li = g_lam_im[h];
    float hr = g_carry_re[c * HH + h];
    float hi = g_carry_im[c * HH + h];
    size_t base = (size_t)c * CLEN * NN + h;
    #pragma unroll 4
    for (int t = 0; t < CLEN; t++) {
        size_t ir = base + (size_t)t * NN;
        float br = g_bu[ir];
        float bi = g_bu[ir + HH];
        float nr = fmaf(lr, hr, fmaf(-li, hi, br));
        float ni = fmaf(lr, hi, fmaf(li, hr, bi));
        hr = nr; hi = ni;
        __nv_bfloat16 a = __float2bfloat16(hr);
        g_h_hi[ir] = a;
        g_h_lo[ir] = __float2bfloat16(hr - __bfloat162float(a));
        __nv_bfloat16 b = __float2bfloat16(hi);
        g_h_hi[ir + HH] = b;
        g_h_lo[ir + HH] = __float2bfloat16(hi - __bfloat162float(b));
    }
}

// ---------------- launch ----------------
extern "C" void kernel_launch(void* const* d_in, const int* in_sizes, int n_in,
                              void* d_out, int out_size) {
    (void)in_sizes; (void)n_in; (void)out_size;
    const float* x         = (const float*)d_in[0];
    const float* nu_log    = (const float*)d_in[1];
    const float* theta_log = (const float*)d_in[2];
    const float* gamma_log = (const float*)d_in[3];
    const float* B_re      = (const float*)d_in[4];
    const float* B_im      = (const float*)d_in[5];
    const float* C_re      = (const float*)d_in[6];
    const float* C_im      = (const float*)d_in[7];
    const float* Dvec      = (const float*)d_in[8];
    float* out = (float*)d_out;

    cudaFuncSetAttribute(gemm_split<0>, cudaFuncAttributeMaxDynamicSharedMemorySize, SMEM_TOT);
    cudaFuncSetAttribute(gemm_split<1>, cudaFuncAttributeMaxDynamicSharedMemorySize, SMEM_TOT);

    init_params<<<(HH + 255) / 256, 256>>>(nu_log, theta_log, gamma_log);
    conv_x_k<<<((size_t)TT * DM) / 1024, 256>>>(x);
    conv_b_k<<<((size_t)NN * KK) / 1024, 256>>>(B_re, B_im);

    dim3 gg(NN / BN, TT / BM);   // (32, 32) = 1024 CTAs
    gemm_split<0><<<gg, 256, SMEM_TOT>>>(x, Dvec, out);

    conv_c_k<<<((size_t)NN * KK) / 1024, 256>>>(C_re, C_im);

    dim3 gs(HH / 256, NCHUNK);
    scan_chunks<<<gs, 256>>>();
    scan_carry<<<HH / 256, 256>>>();
    scan_final<<<gs, 256>>>();

    gemm_split<1><<<gg, 256, SMEM_TOT>>>(x, Dvec, out);
}